// round 15
// baseline (speedup 1.0000x reference)
#include <cuda_runtime.h>
#include <cuda_fp16.h>
#include <cuda_fp8.h>
#include <cstdint>

#define M_DIM 16384
#define N_DIM 4096
#define K_DIM 4096

#define BM 128
#define BN 128
#define BK 64
#define KITERS (K_DIM / BK)            // 64
#define TILE_BYTES 16384               // 128 rows x 64 k x 2B, contiguous & pre-swizzled
#define STAGE_BYTES (2 * TILE_BYTES)
#define GEMM_SMEM (1024 + 3 * STAGE_BYTES)

#define GRID_CTAS 296                  // 2 CTAs/SM x 148 SMs, all resident (persistent)
#define NTILES_TOTAL ((M_DIM / BM) * (N_DIM / BN))   // 4096

#define QX_BLOCKS (M_DIM * (K_DIM / 512) / 8)          // 16384 (warp = 4 k-blocks)
#define QW_BLOCKS ((K_DIM / 64) * (N_DIM / 128))       // 2048

#define SWZ(x) ((x) ^ (((x) >> 3) & 0x70))

// Scratch (device globals: allocation-free rule).
// Tiled layout: g_A[(mt*64 + ch)*16384 + SWZ(row*128 + kc*2)] (bytes), mt=m/128, ch=k/64.
__device__ __align__(1024) __half g_A[(size_t)M_DIM * K_DIM];
__device__ __align__(1024) __half g_B[(size_t)N_DIM * K_DIM];

__device__ __forceinline__ uint32_t smem_u32(const void* p) {
    uint32_t a;
    asm("{ .reg .u64 t; cvta.to.shared.u64 t, %1; cvt.u32.u64 %0, t; }" : "=r"(a) : "l"(p));
    return a;
}

#define MBAR_WAIT(addr, ph) do {                                                                  \
    uint32_t _m = (uint32_t)(addr), _p = (uint32_t)(ph), _d;                                      \
    asm volatile("{\n\t.reg .pred p;\n\t"                                                         \
        "mbarrier.try_wait.parity.acquire.cta.shared::cta.b64 p, [%1], %2;\n\t"                   \
        "selp.b32 %0, 1, 0, p;\n\t}"                                                              \
        : "=r"(_d) : "r"(_m), "r"(_p) : "memory");                                                \
    if (!_d) {                                                                                    \
        asm volatile("{\n\t.reg .pred P1;\n\t"                                                    \
            "WL_%=:\n\t"                                                                          \
            "mbarrier.try_wait.parity.acquire.cta.shared::cta.b64 P1, [%0], %1, 0x989680;\n\t"    \
            "@P1 bra.uni WD_%=;\n\t"                                                              \
            "bra.uni WL_%=;\n\t"                                                                  \
            "WD_%=:\n\t}"                                                                         \
            :: "r"(_m), "r"(_p) : "memory");                                                      \
    }                                                                                             \
} while (0)

__device__ __forceinline__ void bulk_ld(uint32_t dst, const void* src, uint32_t mbar) {
    asm volatile(
        "cp.async.bulk.shared::cta.global.mbarrier::complete_tx::bytes [%0], [%1], %2, [%3];"
        :: "r"(dst), "l"(src), "r"((uint32_t)TILE_BYTES), "r"(mbar) : "memory");
}

// ============================ quantization =================================
// Reproduce: scale = max(amax/448, 1e-12); q = e4m3_rne(x/scale); deq = q*scale.
__device__ __forceinline__ void quant4_inv(const float4 v, float inv, float scale, __half* h) {
    float f[4] = {v.x, v.y, v.z, v.w};
    #pragma unroll
    for (int j = 0; j < 4; j++) {
        __nv_fp8_storage_t q =
            __nv_cvt_float_to_fp8(f[j] * inv, __NV_SATFINITE, __NV_E4M3);
        __half_raw hr = __nv_cvt_fp8_to_halfraw(q, __NV_E4M3);
        float dq = __half2float(*reinterpret_cast<__half*>(&hr)) * scale;
        h[j] = __float2half_rn(dq);
    }
}

__device__ __forceinline__ float amax4(const float4 v) {
    return fmaxf(fmaxf(fabsf(v.x), fabsf(v.y)), fmaxf(fabsf(v.z), fabsf(v.w)));
}

__device__ __forceinline__ float4 ldcs4(const float* p) {
    float4 v;
    asm volatile("ld.global.cs.v4.f32 {%0,%1,%2,%3}, [%4];"
                 : "=f"(v.x), "=f"(v.y), "=f"(v.z), "=f"(v.w) : "l"(p));
    return v;
}

#define WPITCH 264
// w-part CTAs first (their smem-transpose tail overlaps the x DRAM stream).
__global__ void __launch_bounds__(256) quant_fused_kernel(const float* __restrict__ x,
                                                          const float* __restrict__ kn) {
    if (blockIdx.x >= QW_BLOCKS) {
        // ---- x part: warp handles 4 consecutive 128-blocks (512 elems) ----
        int w = (blockIdx.x - QW_BLOCKS) * 8 + (threadIdx.x >> 5);
        int lane = threadIdx.x & 31;
        int m = w >> 3, c = w & 7;                 // chunk of 512 along K
        const float* src = x + (size_t)m * K_DIM + c * 512 + lane * 4;
        float4 v[4];
        #pragma unroll
        for (int j = 0; j < 4; j++) v[j] = ldcs4(src + j * 128);
        float a[4];
        #pragma unroll
        for (int j = 0; j < 4; j++) a[j] = amax4(v[j]);
        #pragma unroll
        for (int o = 16; o; o >>= 1) {
            #pragma unroll
            for (int j = 0; j < 4; j++)
                a[j] = fmaxf(a[j], __shfl_xor_sync(0xFFFFFFFFu, a[j], o));
        }
        char* base = (char*)g_A;
        int mt = m >> 7, row = m & 127;
        #pragma unroll
        for (int j = 0; j < 4; j++) {
            float scale = fmaxf(__fdiv_rn(a[j], 448.0f), 1e-12f);
            float inv = __fdiv_rn(1.0f, scale);
            __half h[4];
            quant4_inv(v[j], inv, scale, h);
            int k0 = c * 512 + j * 128 + lane * 4;
            size_t t = ((size_t)mt * 64 + (k0 >> 6)) * TILE_BYTES +
                       SWZ(row * 128 + (k0 & 63) * 2);
            uint2 u = *(uint2*)h;
            asm volatile("st.global.cs.v2.b32 [%0], {%1,%2};"
                         :: "l"(base + t), "r"(u.x), "r"(u.y) : "memory");
        }
    } else {
        // ---- w part: CTA tile 64 k-rows x 128 n-cols -> g_B [N,K] tiled+swizzled ----
        __shared__ __align__(16) char st[64 * WPITCH];
        int bid = blockIdx.x;
        int tid = threadIdx.x, wid = tid >> 5, lane = tid & 31;
        int kt = bid >> 5, nb = bid & 31;
        int k0 = kt * 64, n0 = nb * 128;

        #pragma unroll
        for (int r = 0; r < 8; r += 2) {
            int kl0 = wid * 8 + r, kl1 = kl0 + 1;
            float4 v0 = ldcs4(kn + (size_t)(k0 + kl0) * N_DIM + n0 + lane * 4);
            float4 v1 = ldcs4(kn + (size_t)(k0 + kl1) * N_DIM + n0 + lane * 4);
            float a0 = amax4(v0), a1 = amax4(v1);
            #pragma unroll
            for (int o = 16; o; o >>= 1) {
                a0 = fmaxf(a0, __shfl_xor_sync(0xFFFFFFFFu, a0, o));
                a1 = fmaxf(a1, __shfl_xor_sync(0xFFFFFFFFu, a1, o));
            }
            float s0 = fmaxf(__fdiv_rn(a0, 448.0f), 1e-12f);
            float s1 = fmaxf(__fdiv_rn(a1, 448.0f), 1e-12f);
            float i0 = __fdiv_rn(1.0f, s0);
            float i1 = __fdiv_rn(1.0f, s1);
            __half h0[4], h1[4];
            quant4_inv(v0, i0, s0, h0);
            quant4_inv(v1, i1, s1, h1);
            *(uint2*)(st + kl0 * WPITCH + lane * 8) = *(uint2*)h0;
            *(uint2*)(st + kl1 * WPITCH + lane * 8) = *(uint2*)h1;
        }
        __syncthreads();

        int n = tid & 127, seg = (tid >> 7) * 32;
        uint16_t vals[32];
        #pragma unroll
        for (int k = 0; k < 32; k++)
            vals[k] = *(const uint16_t*)(st + (seg + k) * WPITCH + n * 2);
        char* base = (char*)g_B;
        size_t tile = ((size_t)nb * 64 + kt) * TILE_BYTES;
        const uint4* src = (const uint4*)vals;
        #pragma unroll
        for (int j = 0; j < 4; j++) {
            size_t doff = tile + SWZ(n * 128 + (seg + j * 8) * 2);
            *(uint4*)(base + doff) = src[j];
        }
    }
}

// ============================ GEMM (persistent, R9 mainloop) ===============
// Tile id -> (mt, nt) with the validated L2 group swizzle.
__device__ __forceinline__ void tile_coords(int t, int& mt, int& nt) {
    int g = t >> 8, r = t & 255;
    mt = g * 8 + (r & 7);
    nt = r >> 3;
}

// smem: [sb..23] full mbars (3x8), [sb+24..47] empty mbars (3x8), tiles at 1024-align.
__global__ void __launch_bounds__(256, 2) gemm_kernel(const float* __restrict__ bias,
                                                      float* __restrict__ out) {
    extern __shared__ char smem_raw[];
    uint32_t sb = smem_u32(smem_raw);
    uint32_t data = (sb + 64 + 1023) & ~1023u;
    int tid = threadIdx.x, wid = tid >> 5, lane = tid & 31;
    int wm = (wid & 3) * 32, wn = (wid >> 2) * 64;

    int slot = blockIdx.x;
    int ntiles = (NTILES_TOTAL - slot + GRID_CTAS - 1) / GRID_CTAS;
    int total_lc = ntiles * KITERS;

    if (tid == 0) {
        #pragma unroll
        for (int s = 0; s < 3; s++) {
            asm volatile("mbarrier.init.shared.b64 [%0], 1;" :: "r"(sb + s * 8) : "memory");
            asm volatile("mbarrier.init.shared.b64 [%0], 8;" :: "r"(sb + 24 + s * 8) : "memory");
        }
    }
    __syncthreads();

    if (tid == 0) {
        asm volatile("fence.proxy.async.shared::cta;" ::: "memory");
        int mt0, nt0;
        tile_coords(slot, mt0, nt0);
        const char* pA = (const char*)g_A + (size_t)mt0 * 64 * TILE_BYTES;
        const char* pB = (const char*)g_B + (size_t)nt0 * 64 * TILE_BYTES;
        #pragma unroll
        for (int s = 0; s < 3; s++) {
            asm volatile("mbarrier.arrive.expect_tx.shared.b64 _, [%0], %1;"
                         :: "r"(sb + s * 8), "r"((uint32_t)STAGE_BYTES) : "memory");
            bulk_ld(data + s * STAGE_BYTES, pA + s * TILE_BYTES, sb + s * 8);
            bulk_ld(data + s * STAGE_BYTES + TILE_BYTES, pB + s * TILE_BYTES, sb + s * 8);
        }
    }

    for (int j = 0; j < ntiles; j++) {
        int t = slot + j * GRID_CTAS;
        int mt, nt;
        tile_coords(t, mt, nt);
        size_t m0 = (size_t)mt * BM, n0 = (size_t)nt * BN;

        float d[2][8][4];
        #pragma unroll
        for (int i = 0; i < 2; i++)
            #pragma unroll
            for (int jj = 0; jj < 8; jj++)
                #pragma unroll
                for (int q = 0; q < 4; q++) d[i][jj][q] = 0.0f;

        for (int it = 0; it < KITERS; it++) {
            int lc = j * KITERS + it;
            int s = lc % 3;
            int ph = (lc / 3) & 1;
            MBAR_WAIT(sb + s * 8, ph);

            uint32_t sA = data + s * STAGE_BYTES;
            uint32_t sB = sA + TILE_BYTES;

            #pragma unroll
            for (int ks = 0; ks < 4; ks++) {
                uint32_t a[2][4], b[8][2];
                #pragma unroll
                for (int am = 0; am < 2; am++) {
                    int row = wm + am * 16 + (lane & 15);
                    int cb = ks * 32 + (lane >> 4) * 16;
                    uint32_t addr = sA + row * 128 + (cb ^ ((row & 7) * 16));
                    asm volatile("ldmatrix.sync.aligned.m8n8.x4.shared.b16 {%0,%1,%2,%3}, [%4];"
                                 : "=r"(a[am][0]), "=r"(a[am][1]), "=r"(a[am][2]), "=r"(a[am][3])
                                 : "r"(addr));
                }
                #pragma unroll
                for (int q = 0; q < 4; q++) {
                    int grp = lane >> 3, rin = lane & 7;
                    int nrow = wn + q * 16 + ((grp >> 1) << 3) + rin;
                    int kcol = ks * 16 + ((grp & 1) << 3);
                    uint32_t addr = sB + nrow * 128 + ((kcol * 2) ^ ((nrow & 7) * 16));
                    uint32_t r0, r1, r2, r3;
                    asm volatile("ldmatrix.sync.aligned.m8n8.x4.shared.b16 {%0,%1,%2,%3}, [%4];"
                                 : "=r"(r0), "=r"(r1), "=r"(r2), "=r"(r3) : "r"(addr));
                    b[q * 2][0] = r0;     b[q * 2][1] = r1;
                    b[q * 2 + 1][0] = r2; b[q * 2 + 1][1] = r3;
                }
                #pragma unroll
                for (int am = 0; am < 2; am++)
                    #pragma unroll
                    for (int bn = 0; bn < 8; bn++) {
                        asm volatile(
                            "mma.sync.aligned.m16n8k16.row.col.f32.f16.f16.f32 "
                            "{%0,%1,%2,%3}, {%4,%5,%6,%7}, {%8,%9}, {%0,%1,%2,%3};"
                            : "+f"(d[am][bn][0]), "+f"(d[am][bn][1]),
                              "+f"(d[am][bn][2]), "+f"(d[am][bn][3])
                            : "r"(a[am][0]), "r"(a[am][1]), "r"(a[am][2]), "r"(a[am][3]),
                              "r"(b[bn][0]), "r"(b[bn][1]));
                    }
            }

            // Release stage s (after MMAs consumed its data).
            if (lane == 0)
                asm volatile("mbarrier.arrive.shared.b64 _, [%0];"
                             :: "r"(sb + 24 + s * 8) : "memory");
            // Producer: refill stage s with chunk lc+3 (may belong to next tile,
            // so the next tile's pipeline fills during this tile's tail+epilogue).
            if (tid == 0 && lc + 3 < total_lc) {
                int lp = lc + 3;
                int jp = lp >> 6, cp = lp & 63;
                int tp = slot + jp * GRID_CTAS;
                int mtp, ntp;
                tile_coords(tp, mtp, ntp);
                const char* pA = (const char*)g_A + ((size_t)mtp * 64 + cp) * TILE_BYTES;
                const char* pB = (const char*)g_B + ((size_t)ntp * 64 + cp) * TILE_BYTES;
                MBAR_WAIT(sb + 24 + s * 8, ph);
                asm volatile("mbarrier.arrive.expect_tx.shared.b64 _, [%0], %1;"
                             :: "r"(sb + s * 8), "r"((uint32_t)STAGE_BYTES) : "memory");
                bulk_ld(sA, pA, sb + s * 8);
                bulk_ld(sB, pB, sb + s * 8);
            }
        }

        // Epilogue for tile j (streaming stores, add bias). Next tile's chunks
        // are already in flight.
        #pragma unroll
        for (int am = 0; am < 2; am++) {
            size_t row0 = m0 + wm + am * 16 + (lane >> 2);
            #pragma unroll
            for (int bn = 0; bn < 8; bn++) {
                size_t col = n0 + wn + bn * 8 + (lane & 3) * 2;
                float2 bv = *(const float2*)(bias + col);
                float x0 = d[am][bn][0] + bv.x, y0 = d[am][bn][1] + bv.y;
                float x1 = d[am][bn][2] + bv.x, y1 = d[am][bn][3] + bv.y;
                float* p0 = out + row0 * N_DIM + col;
                float* p1 = out + (row0 + 8) * N_DIM + col;
                asm volatile("st.global.cs.v2.f32 [%0], {%1,%2};" :: "l"(p0), "f"(x0), "f"(y0)
                             : "memory");
                asm volatile("st.global.cs.v2.f32 [%0], {%1,%2};" :: "l"(p1), "f"(x1), "f"(y1)
                             : "memory");
            }
        }
    }
}

// ============================ launch =======================================
extern "C" void kernel_launch(void* const* d_in, const int* in_sizes, int n_in,
                              void* d_out, int out_size) {
    const float* x    = (const float*)d_in[0];
    const float* kn   = (const float*)d_in[1];
    const float* bias = (const float*)d_in[2];
    float* out = (float*)d_out;

    quant_fused_kernel<<<QX_BLOCKS + QW_BLOCKS, 256>>>(x, kn);

    cudaFuncSetAttribute(gemm_kernel, cudaFuncAttributeMaxDynamicSharedMemorySize, GEMM_SMEM);
    gemm_kernel<<<GRID_CTAS, 256, GEMM_SMEM>>>(bias, out);
}

// round 16
// speedup vs baseline: 1.0672x; 1.0672x over previous
#include <cuda_runtime.h>
#include <cuda_fp16.h>
#include <cuda_fp8.h>
#include <cstdint>

#define M_DIM 16384
#define N_DIM 4096
#define K_DIM 4096

#define BM 128
#define BN 128
#define BK 64
#define KITERS (K_DIM / BK)            // 64
#define TILE_BYTES 16384               // 128 rows x 64 k x 2B, contiguous & pre-swizzled
#define STAGE_BYTES (2 * TILE_BYTES)
#define GEMM_SMEM (1024 + 3 * STAGE_BYTES)

#define QX_BLOCKS (M_DIM * (K_DIM / 512) / 8)          // 16384 (warp = 4 k-blocks)
#define QW_BLOCKS ((K_DIM / 64) * (N_DIM / 128))       // 2048

#define SWZ(x) ((x) ^ (((x) >> 3) & 0x70))

// Scratch (device globals: allocation-free rule).
// Tiled layout: g_A[(mt*64 + ch)*16384 + SWZ(row*128 + kc*2)] (bytes), mt=m/128, ch=k/64.
__device__ __align__(1024) __half g_A[(size_t)M_DIM * K_DIM];
__device__ __align__(1024) __half g_B[(size_t)N_DIM * K_DIM];

__device__ __forceinline__ uint32_t smem_u32(const void* p) {
    uint32_t a;
    asm("{ .reg .u64 t; cvta.to.shared.u64 t, %1; cvt.u32.u64 %0, t; }" : "=r"(a) : "l"(p));
    return a;
}

#define MBAR_WAIT(addr, ph) do {                                                                  \
    uint32_t _m = (uint32_t)(addr), _p = (uint32_t)(ph), _d;                                      \
    asm volatile("{\n\t.reg .pred p;\n\t"                                                         \
        "mbarrier.try_wait.parity.acquire.cta.shared::cta.b64 p, [%1], %2;\n\t"                   \
        "selp.b32 %0, 1, 0, p;\n\t}"                                                              \
        : "=r"(_d) : "r"(_m), "r"(_p) : "memory");                                                \
    if (!_d) {                                                                                    \
        asm volatile("{\n\t.reg .pred P1;\n\t"                                                    \
            "WL_%=:\n\t"                                                                          \
            "mbarrier.try_wait.parity.acquire.cta.shared::cta.b64 P1, [%0], %1, 0x989680;\n\t"    \
            "@P1 bra.uni WD_%=;\n\t"                                                              \
            "bra.uni WL_%=;\n\t"                                                                  \
            "WD_%=:\n\t}"                                                                         \
            :: "r"(_m), "r"(_p) : "memory");                                                      \
    }                                                                                             \
} while (0)

__device__ __forceinline__ void bulk_ld(uint32_t dst, const void* src, uint32_t mbar) {
    asm volatile(
        "cp.async.bulk.shared::cta.global.mbarrier::complete_tx::bytes [%0], [%1], %2, [%3];"
        :: "r"(dst), "l"(src), "r"((uint32_t)TILE_BYTES), "r"(mbar) : "memory");
}

// ============================ quantization =================================
// Reproduce: scale = max(amax/448, 1e-12); q = e4m3_rne(x/scale); deq = q*scale.
// One reciprocal per block; per-element multiply (<=1ulp vs divide, negligible
// effect on the e4m3 rounding decision).
__device__ __forceinline__ void quant4_inv(const float4 v, float inv, float scale, __half* h) {
    float f[4] = {v.x, v.y, v.z, v.w};
    #pragma unroll
    for (int j = 0; j < 4; j++) {
        __nv_fp8_storage_t q =
            __nv_cvt_float_to_fp8(f[j] * inv, __NV_SATFINITE, __NV_E4M3);
        __half_raw hr = __nv_cvt_fp8_to_halfraw(q, __NV_E4M3);
        float dq = __half2float(*reinterpret_cast<__half*>(&hr)) * scale;
        h[j] = __float2half_rn(dq);
    }
}

__device__ __forceinline__ float amax4(const float4 v) {
    return fmaxf(fmaxf(fabsf(v.x), fabsf(v.y)), fmaxf(fabsf(v.z), fabsf(v.w)));
}

__device__ __forceinline__ float4 ldcs4(const float* p) {
    float4 v;
    asm volatile("ld.global.cs.v4.f32 {%0,%1,%2,%3}, [%4];"
                 : "=f"(v.x), "=f"(v.y), "=f"(v.z), "=f"(v.w) : "l"(p));
    return v;
}

#define WPITCH 264
// w-part CTAs first (their smem-transpose tail overlaps the x DRAM stream).
__global__ void __launch_bounds__(256) quant_fused_kernel(const float* __restrict__ x,
                                                          const float* __restrict__ kn) {
    if (blockIdx.x >= QW_BLOCKS) {
        // ---- x part: warp handles 4 consecutive 128-blocks (512 elems) ----
        int w = (blockIdx.x - QW_BLOCKS) * 8 + (threadIdx.x >> 5);
        int lane = threadIdx.x & 31;
        int m = w >> 3, c = w & 7;                 // chunk of 512 along K
        const float* src = x + (size_t)m * K_DIM + c * 512 + lane * 4;
        float4 v[4];
        #pragma unroll
        for (int j = 0; j < 4; j++) v[j] = ldcs4(src + j * 128);
        float a[4];
        #pragma unroll
        for (int j = 0; j < 4; j++) a[j] = amax4(v[j]);
        #pragma unroll
        for (int o = 16; o; o >>= 1) {
            #pragma unroll
            for (int j = 0; j < 4; j++)
                a[j] = fmaxf(a[j], __shfl_xor_sync(0xFFFFFFFFu, a[j], o));
        }
        char* base = (char*)g_A;
        int mt = m >> 7, row = m & 127;
        #pragma unroll
        for (int j = 0; j < 4; j++) {
            float scale = fmaxf(__fdiv_rn(a[j], 448.0f), 1e-12f);
            float inv = __fdiv_rn(1.0f, scale);
            __half h[4];
            quant4_inv(v[j], inv, scale, h);
            int k0 = c * 512 + j * 128 + lane * 4;
            size_t t = ((size_t)mt * 64 + (k0 >> 6)) * TILE_BYTES +
                       SWZ(row * 128 + (k0 & 63) * 2);
            uint2 u = *(uint2*)h;
            asm volatile("st.global.cs.v2.b32 [%0], {%1,%2};"
                         :: "l"(base + t), "r"(u.x), "r"(u.y) : "memory");
        }
    } else {
        // ---- w part: CTA tile 64 k-rows x 128 n-cols -> g_B [N,K] tiled+swizzled ----
        __shared__ __align__(16) char st[64 * WPITCH];
        int bid = blockIdx.x;
        int tid = threadIdx.x, wid = tid >> 5, lane = tid & 31;
        int kt = bid >> 5, nb = bid & 31;
        int k0 = kt * 64, n0 = nb * 128;

        #pragma unroll
        for (int r = 0; r < 8; r += 2) {
            int kl0 = wid * 8 + r, kl1 = kl0 + 1;
            float4 v0 = ldcs4(kn + (size_t)(k0 + kl0) * N_DIM + n0 + lane * 4);
            float4 v1 = ldcs4(kn + (size_t)(k0 + kl1) * N_DIM + n0 + lane * 4);
            float a0 = amax4(v0), a1 = amax4(v1);
            #pragma unroll
            for (int o = 16; o; o >>= 1) {
                a0 = fmaxf(a0, __shfl_xor_sync(0xFFFFFFFFu, a0, o));
                a1 = fmaxf(a1, __shfl_xor_sync(0xFFFFFFFFu, a1, o));
            }
            float s0 = fmaxf(__fdiv_rn(a0, 448.0f), 1e-12f);
            float s1 = fmaxf(__fdiv_rn(a1, 448.0f), 1e-12f);
            float i0 = __fdiv_rn(1.0f, s0);
            float i1 = __fdiv_rn(1.0f, s1);
            __half h0[4], h1[4];
            quant4_inv(v0, i0, s0, h0);
            quant4_inv(v1, i1, s1, h1);
            *(uint2*)(st + kl0 * WPITCH + lane * 8) = *(uint2*)h0;
            *(uint2*)(st + kl1 * WPITCH + lane * 8) = *(uint2*)h1;
        }
        __syncthreads();

        int n = tid & 127, seg = (tid >> 7) * 32;
        uint16_t vals[32];
        #pragma unroll
        for (int k = 0; k < 32; k++)
            vals[k] = *(const uint16_t*)(st + (seg + k) * WPITCH + n * 2);
        char* base = (char*)g_B;
        size_t tile = ((size_t)nb * 64 + kt) * TILE_BYTES;
        const uint4* src = (const uint4*)vals;
        #pragma unroll
        for (int j = 0; j < 4; j++) {
            size_t doff = tile + SWZ(n * 128 + (seg + j * 8) * 2);
            *(uint4*)(base + doff) = src[j];
        }
    }
}

// ============================ GEMM (R9 configuration) ======================
// smem: [sb..23] full mbars (3x8), [sb+24..47] empty mbars (3x8), tiles at 1024-align.
__global__ void __launch_bounds__(256, 2) gemm_kernel(const float* __restrict__ bias,
                                                      float* __restrict__ out) {
    extern __shared__ char smem_raw[];
    uint32_t sb = smem_u32(smem_raw);
    uint32_t data = (sb + 64 + 1023) & ~1023u;
    int tid = threadIdx.x, wid = tid >> 5, lane = tid & 31;

    int bid = blockIdx.x;
    int g = bid >> 8, r = bid & 255;
    int mt = g * 8 + (r & 7);
    int nt = r >> 3;
    size_t m0 = (size_t)mt * BM, n0 = (size_t)nt * BN;
    int wm = (wid & 3) * 32, wn = (wid >> 2) * 64;

    const char* srcA = (const char*)g_A + (size_t)mt * 64 * TILE_BYTES;
    const char* srcB = (const char*)g_B + (size_t)nt * 64 * TILE_BYTES;

    if (tid == 0) {
        #pragma unroll
        for (int s = 0; s < 3; s++) {
            asm volatile("mbarrier.init.shared.b64 [%0], 1;" :: "r"(sb + s * 8) : "memory");
            asm volatile("mbarrier.init.shared.b64 [%0], 8;" :: "r"(sb + 24 + s * 8) : "memory");
        }
    }
    __syncthreads();

    if (tid == 0) {
        asm volatile("fence.proxy.async.shared::cta;" ::: "memory");
        #pragma unroll
        for (int s = 0; s < 3; s++) {
            asm volatile("mbarrier.arrive.expect_tx.shared.b64 _, [%0], %1;"
                         :: "r"(sb + s * 8), "r"((uint32_t)STAGE_BYTES) : "memory");
            bulk_ld(data + s * STAGE_BYTES, srcA + s * TILE_BYTES, sb + s * 8);
            bulk_ld(data + s * STAGE_BYTES + TILE_BYTES, srcB + s * TILE_BYTES, sb + s * 8);
        }
    }

    float d[2][8][4];
    #pragma unroll
    for (int i = 0; i < 2; i++)
        #pragma unroll
        for (int j = 0; j < 8; j++)
            #pragma unroll
            for (int q = 0; q < 4; q++) d[i][j][q] = 0.0f;

    for (int it = 0; it < KITERS; it++) {
        int s = it % 3;
        int ph = (it / 3) & 1;
        MBAR_WAIT(sb + s * 8, ph);

        uint32_t sA = data + s * STAGE_BYTES;
        uint32_t sB = sA + TILE_BYTES;

        #pragma unroll
        for (int ks = 0; ks < 4; ks++) {
            uint32_t a[2][4], b[8][2];
            #pragma unroll
            for (int am = 0; am < 2; am++) {
                int row = wm + am * 16 + (lane & 15);
                int cb = ks * 32 + (lane >> 4) * 16;
                uint32_t addr = sA + row * 128 + (cb ^ ((row & 7) * 16));
                asm volatile("ldmatrix.sync.aligned.m8n8.x4.shared.b16 {%0,%1,%2,%3}, [%4];"
                             : "=r"(a[am][0]), "=r"(a[am][1]), "=r"(a[am][2]), "=r"(a[am][3])
                             : "r"(addr));
            }
            #pragma unroll
            for (int q = 0; q < 4; q++) {
                int grp = lane >> 3, rin = lane & 7;
                int nrow = wn + q * 16 + ((grp >> 1) << 3) + rin;
                int kcol = ks * 16 + ((grp & 1) << 3);
                uint32_t addr = sB + nrow * 128 + ((kcol * 2) ^ ((nrow & 7) * 16));
                uint32_t r0, r1, r2, r3;
                asm volatile("ldmatrix.sync.aligned.m8n8.x4.shared.b16 {%0,%1,%2,%3}, [%4];"
                             : "=r"(r0), "=r"(r1), "=r"(r2), "=r"(r3) : "r"(addr));
                b[q * 2][0] = r0;     b[q * 2][1] = r1;
                b[q * 2 + 1][0] = r2; b[q * 2 + 1][1] = r3;
            }
            #pragma unroll
            for (int am = 0; am < 2; am++)
                #pragma unroll
                for (int bn = 0; bn < 8; bn++) {
                    asm volatile(
                        "mma.sync.aligned.m16n8k16.row.col.f32.f16.f16.f32 "
                        "{%0,%1,%2,%3}, {%4,%5,%6,%7}, {%8,%9}, {%0,%1,%2,%3};"
                        : "+f"(d[am][bn][0]), "+f"(d[am][bn][1]),
                          "+f"(d[am][bn][2]), "+f"(d[am][bn][3])
                        : "r"(a[am][0]), "r"(a[am][1]), "r"(a[am][2]), "r"(a[am][3]),
                          "r"(b[bn][0]), "r"(b[bn][1]));
                }
        }

        // Release stage s: one arrival per warp (after MMAs consumed its data).
        if (lane == 0)
            asm volatile("mbarrier.arrive.shared.b64 _, [%0];"
                         :: "r"(sb + 24 + s * 8) : "memory");
        // Producer: thread 0 waits for all 8 releases, then refills stage s.
        if (tid == 0 && it + 3 < KITERS) {
            MBAR_WAIT(sb + 24 + s * 8, ph);
            asm volatile("mbarrier.arrive.expect_tx.shared.b64 _, [%0], %1;"
                         :: "r"(sb + s * 8), "r"((uint32_t)STAGE_BYTES) : "memory");
            bulk_ld(sA, srcA + (size_t)(it + 3) * TILE_BYTES, sb + s * 8);
            bulk_ld(sB, srcB + (size_t)(it + 3) * TILE_BYTES, sb + s * 8);
        }
    }

    // Epilogue: direct register -> gmem (streaming stores), add bias.
    #pragma unroll
    for (int am = 0; am < 2; am++) {
        size_t row0 = m0 + wm + am * 16 + (lane >> 2);
        #pragma unroll
        for (int bn = 0; bn < 8; bn++) {
            size_t col = n0 + wn + bn * 8 + (lane & 3) * 2;
            float2 bv = *(const float2*)(bias + col);
            float x0 = d[am][bn][0] + bv.x, y0 = d[am][bn][1] + bv.y;
            float x1 = d[am][bn][2] + bv.x, y1 = d[am][bn][3] + bv.y;
            float* p0 = out + row0 * N_DIM + col;
            float* p1 = out + (row0 + 8) * N_DIM + col;
            asm volatile("st.global.cs.v2.f32 [%0], {%1,%2};" :: "l"(p0), "f"(x0), "f"(y0)
                         : "memory");
            asm volatile("st.global.cs.v2.f32 [%0], {%1,%2};" :: "l"(p1), "f"(x1), "f"(y1)
                         : "memory");
        }
    }
}

// ============================ launch =======================================
extern "C" void kernel_launch(void* const* d_in, const int* in_sizes, int n_in,
                              void* d_out, int out_size) {
    const float* x    = (const float*)d_in[0];
    const float* kn   = (const float*)d_in[1];
    const float* bias = (const float*)d_in[2];
    float* out = (float*)d_out;

    quant_fused_kernel<<<QX_BLOCKS + QW_BLOCKS, 256>>>(x, kn);

    cudaFuncSetAttribute(gemm_kernel, cudaFuncAttributeMaxDynamicSharedMemorySize, GEMM_SMEM);
    gemm_kernel<<<(M_DIM / BM) * (N_DIM / BN), 256, GEMM_SMEM>>>(bias, out);
}